// round 7
// baseline (speedup 1.0000x reference)
#include <cuda_runtime.h>
#include <cstdint>

using ull = unsigned long long;

#define VOC 95
#define TT  256
#define BB  2048

// ---------------- scratch: xp = x @ Wih1^T + bih1  [B*T, 96] ----------------
__device__ float g_xp[(size_t)BB * TT * 96];

// ---------- packed fp32x2 helpers ----------
__device__ __forceinline__ ull pk2(float w) {
    ull d; unsigned r = __float_as_uint(w);
    asm("mov.b64 %0, {%1,%1};" : "=l"(d) : "r"(r));
    return d;
}
__device__ __forceinline__ ull pkf(float a, float b) {
    ull d;
    asm("mov.b64 %0, {%1,%2};" : "=l"(d)
        : "r"(__float_as_uint(a)), "r"(__float_as_uint(b)));
    return d;
}
__device__ __forceinline__ float2 up2(ull v) {
    unsigned lo, hi;
    asm("mov.b64 {%0,%1}, %2;" : "=r"(lo), "=r"(hi) : "l"(v));
    return make_float2(__uint_as_float(lo), __uint_as_float(hi));
}
__device__ __forceinline__ void fma2(ull& d, ull a, ull b) {
    asm("fma.rn.f32x2 %0, %1, %2, %0;" : "+l"(d) : "l"(a), "l"(b));
}
__device__ __forceinline__ ull add2(ull a, ull b) {
    ull d; asm("add.rn.f32x2 %0, %1, %2;" : "=l"(d) : "l"(a), "l"(b));
    return d;
}

// ---------- activations (MUFU tanh.approx) ----------
__device__ __forceinline__ float tanhap(float v) {
    float r; asm("tanh.approx.f32 %0, %1;" : "=f"(r) : "f"(v)); return r;
}
__device__ __forceinline__ float fsig(float v) {
    return fmaf(tanhap(0.5f * v), 0.5f, 0.5f);
}

extern __shared__ float smem[];

// GMEM weight [3*32, isz] -> SMEM [g][c][lane][4] (i >= isz zero-padded)
__device__ __forceinline__ void load_wmat(float* dst, const float* __restrict__ src,
                                          int C, int isz, int tid, int nthr)
{
    int n = 3 * C * 128;
    for (int idx = tid; idx < n; idx += nthr) {
        int q = idx & 3, jj = (idx >> 2) & 31;
        int c = (idx >> 7) % C, g = idx / (C * 128);
        int i = c * 4 + q;
        dst[idx] = (i < isz) ? src[(g * 32 + jj) * isz + i] : 0.f;
    }
}

// ============================================================================
// Kernel 1: xp[r][96] = x[r][95] @ Wih1^T + bih1   (parallel over all B*T rows)
// ============================================================================
#define K1_NB   256
#define K1_NT   256
#define K1_XS   9216
#define K1_SMEM_FLOATS (9216 + 8 * 8 * 96 * 2)
#define K1_SMEM_BYTES  (K1_SMEM_FLOATS * 4)

__global__ void __launch_bounds__(K1_NT, 2)
gru_xproj(const float* __restrict__ x,
          const float* __restrict__ Wih1,
          const float* __restrict__ bih1)
{
    const int tid = threadIdx.x;
    load_wmat(smem, Wih1, 24, VOC, tid, K1_NT);
    __syncthreads();

    const int w = tid >> 5, j = tid & 31;
    float2* xsw = (float2*)(smem + K1_XS) + (size_t)w * (8 * 96);

    const ull bR = pk2(bih1[j]), bZ = pk2(bih1[32 + j]), bN = pk2(bih1[64 + j]);
    const size_t pairBase = ((size_t)blockIdx.x * 8 + w) * 128;

#pragma unroll 1
    for (int it = 0; it < 16; it++) {
        const size_t p0 = pairBase + (size_t)it * 8;

#pragma unroll
        for (int p = 0; p < 8; p++) {
            size_t r0 = (p0 + p) * 2, r1 = r0 + 1;
#pragma unroll
            for (int k = 0; k < 3; k++) {
                int i = j + 32 * k;
                float a = 0.f, b = 0.f;
                if (i < VOC) {
                    a = __ldcs(x + r0 * VOC + i);
                    b = __ldcs(x + r1 * VOC + i);
                }
                xsw[p * 96 + i] = make_float2(a, b);
            }
        }
        __syncwarp();

        ull acc[8][3];
#pragma unroll
        for (int p = 0; p < 8; p++) { acc[p][0] = bR; acc[p][1] = bZ; acc[p][2] = bN; }

#pragma unroll 2
        for (int c = 0; c < 24; c++) {
            float4 wA = *(const float4*)(smem + ((0 * 24 + c) * 32 + j) * 4);
            float4 wB = *(const float4*)(smem + ((1 * 24 + c) * 32 + j) * 4);
            float4 wC = *(const float4*)(smem + ((2 * 24 + c) * 32 + j) * 4);
            ull a0 = pk2(wA.x), a1 = pk2(wA.y), a2 = pk2(wA.z), a3 = pk2(wA.w);
            ull b0 = pk2(wB.x), b1 = pk2(wB.y), b2 = pk2(wB.z), b3 = pk2(wB.w);
            ull c0 = pk2(wC.x), c1 = pk2(wC.y), c2 = pk2(wC.z), c3 = pk2(wC.w);
#pragma unroll
            for (int p = 0; p < 8; p++) {
                ulonglong2 x01 = *(const ulonglong2*)(xsw + p * 96 + 4 * c);
                ulonglong2 x23 = *(const ulonglong2*)(xsw + p * 96 + 4 * c + 2);
                fma2(acc[p][0], x01.x, a0); fma2(acc[p][0], x01.y, a1);
                fma2(acc[p][0], x23.x, a2); fma2(acc[p][0], x23.y, a3);
                fma2(acc[p][1], x01.x, b0); fma2(acc[p][1], x01.y, b1);
                fma2(acc[p][1], x23.x, b2); fma2(acc[p][1], x23.y, b3);
                fma2(acc[p][2], x01.x, c0); fma2(acc[p][2], x01.y, c1);
                fma2(acc[p][2], x23.x, c2); fma2(acc[p][2], x23.y, c3);
            }
        }

#pragma unroll
        for (int p = 0; p < 8; p++) {
            size_t r0 = (p0 + p) * 2, r1 = r0 + 1;
#pragma unroll
            for (int g = 0; g < 3; g++) {
                float2 v = up2(acc[p][g]);
                g_xp[r0 * 96 + g * 32 + j] = v.x;
                g_xp[r1 * 96 + g * 32 + j] = v.y;
            }
        }
        __syncwarp();
    }
}

// ============================================================================
// Kernel 2: layer-pipelined warp-specialized scan.
// 128 blocks x 8 warps; block owns 16 rows (8 packed pairs).
// Stage skew: L1@t=tau, L2i@tau-1, L2h@tau-2, L3i@tau-3, L3h@tau-4, FC@tau-5.
// ============================================================================
#define NT2 256
#define NB2 128

// weight float offsets
#define OW1H 0
#define OW2I 3072
#define OW2H 6144
#define OW3I 9216
#define OW3H 12288
#define OWFC 15360
#define ORING 18432      // rings start (floats)
// float2 offsets relative to ring base
#define RH1  0           // [2 slots][8 pairs][32]
#define RXI2 512         // [2][8][96]
#define RH2  2048        // [2][8][32]
#define RXI3 2560        // [2][8][96]
#define RH3  4096        // [2][8][32]
#define RING_F2 4608
#define SC_SMEM_FLOATS (ORING + RING_F2 * 2)
#define SC_SMEM_BYTES  (SC_SMEM_FLOATS * 4)

// 3-gate projection over P pairs; weights loaded once per chunk, reused for all P.
// in: pair-0 base; pairs strided 32 float2.
template<int P>
__device__ __forceinline__ void proj_multi(const float* __restrict__ W, int j,
                                           const float2* __restrict__ in,
                                           ull (&acc)[P][3])
{
#pragma unroll
    for (int c = 0; c < 8; c++) {
        float4 wA = *(const float4*)(W + ((0 * 8 + c) * 32 + j) * 4);
        float4 wB = *(const float4*)(W + ((1 * 8 + c) * 32 + j) * 4);
        float4 wC = *(const float4*)(W + ((2 * 8 + c) * 32 + j) * 4);
        ull a0 = pk2(wA.x), a1 = pk2(wA.y), a2 = pk2(wA.z), a3 = pk2(wA.w);
        ull b0 = pk2(wB.x), b1 = pk2(wB.y), b2 = pk2(wB.z), b3 = pk2(wB.w);
        ull c0 = pk2(wC.x), c1 = pk2(wC.y), c2 = pk2(wC.z), c3 = pk2(wC.w);
#pragma unroll
        for (int p = 0; p < P; p++) {
            ulonglong2 x01 = *(const ulonglong2*)(in + p * 32 + 4 * c);
            ulonglong2 x23 = *(const ulonglong2*)(in + p * 32 + 4 * c + 2);
            fma2(acc[p][0], x01.x, a0); fma2(acc[p][0], x01.y, a1);
            fma2(acc[p][0], x23.x, a2); fma2(acc[p][0], x23.y, a3);
            fma2(acc[p][1], x01.x, b0); fma2(acc[p][1], x01.y, b1);
            fma2(acc[p][1], x23.x, b2); fma2(acc[p][1], x23.y, b3);
            fma2(acc[p][2], x01.x, c0); fma2(acc[p][2], x01.y, c1);
            fma2(acc[p][2], x23.x, c2); fma2(acc[p][2], x23.y, c3);
        }
    }
}

// GRU elementwise for one packed pair
__device__ __forceinline__ ull gru_pair(ull aR, ull aZ, ull aNx, ull aNh, ull h)
{
    float2 r2 = up2(aR), z2 = up2(aZ), nx = up2(aNx), nh = up2(aNh), hh = up2(h);
    float r0 = fsig(r2.x), r1 = fsig(r2.y);
    float z0 = fsig(z2.x), z1 = fsig(z2.y);
    float n0 = tanhap(nx.x + r0 * nh.x);
    float n1 = tanhap(nx.y + r1 * nh.y);
    float h0 = n0 + z0 * (hh.x - n0);
    float h1 = n1 + z1 * (hh.y - n1);
    return pkf(h0, h1);
}

// input-proj stage (L2i / L3i): proj h-ring -> xi-ring
template<int P>
__device__ __forceinline__ void stage_iproj(const float* __restrict__ W, int j,
                                            const float2* __restrict__ hring,
                                            float2* xiring, int lo, int t,
                                            ull b0, ull b1, ull b2)
{
    ull acc[P][3];
#pragma unroll
    for (int p = 0; p < P; p++) { acc[p][0] = b0; acc[p][1] = b1; acc[p][2] = b2; }
    proj_multi<P>(W, j, hring + lo * 32, acc);
    float2* xo = xiring + (size_t)(t & 1) * 768 + lo * 96;
#pragma unroll
    for (int p = 0; p < P; p++)
#pragma unroll
        for (int g = 0; g < 3; g++)
            *(ull*)(xo + p * 96 + g * 32 + j) = acc[p][g];
}

// hidden-recurrence stage (L2h / L3h): proj own h ring + combine xi-ring + ew
template<int P>
__device__ __forceinline__ void stage_hrec(const float* __restrict__ W, int j,
                                           float2* hring, const float2* xiring,
                                           int lo, int t,
                                           ull b0, ull b1, ull b2)
{
    const float2* hold_base = hring + (size_t)((t - 1) & 1) * 256;
    ull acc[P][3];
#pragma unroll
    for (int p = 0; p < P; p++) { acc[p][0] = b0; acc[p][1] = b1; acc[p][2] = b2; }
    proj_multi<P>(W, j, hold_base + lo * 32, acc);
    const float2* xi = xiring + (size_t)(t & 1) * 768 + lo * 96;
    float2* hnew = hring + (size_t)(t & 1) * 256 + lo * 32;
#pragma unroll
    for (int p = 0; p < P; p++) {
        ull x0 = *(const ull*)(xi + p * 96 + j);
        ull x1 = *(const ull*)(xi + p * 96 + 32 + j);
        ull x2 = *(const ull*)(xi + p * 96 + 64 + j);
        ull ho = *(const ull*)(hold_base + (lo + p) * 32 + j);
        ull hn = gru_pair(add2(x0, acc[p][0]), add2(x1, acc[p][1]),
                          x2, acc[p][2], ho);
        *(ull*)(hnew + p * 32 + j) = hn;
    }
}

// FC stage: proj h3 ring -> out
template<int P>
__device__ __forceinline__ void stage_fc(const float* __restrict__ W, int j,
                                         const float2* h3ring, int lo, int t,
                                         int rb, float* __restrict__ out,
                                         ull b0, ull b1, ull b2)
{
    ull acc[P][3];
#pragma unroll
    for (int p = 0; p < P; p++) { acc[p][0] = b0; acc[p][1] = b1; acc[p][2] = b2; }
    proj_multi<P>(W, j, h3ring + (size_t)(t & 1) * 256 + lo * 32, acc);
#pragma unroll
    for (int p = 0; p < P; p++) {
        size_t base0 = ((size_t)(rb + 2 * (lo + p)) * TT + t) * VOC;
        size_t base1 = base0 + (size_t)TT * VOC;
        float2 v;
        v = up2(acc[p][0]); __stcs(out + base0 + j, v.x);      __stcs(out + base1 + j, v.y);
        v = up2(acc[p][1]); __stcs(out + base0 + 32 + j, v.x); __stcs(out + base1 + 32 + j, v.y);
        if (64 + j < VOC) {
            v = up2(acc[p][2]); __stcs(out + base0 + 64 + j, v.x); __stcs(out + base1 + 64 + j, v.y);
        }
    }
}

__global__ void __launch_bounds__(NT2, 1)
gru_scan(const float* __restrict__ Whh1, const float* __restrict__ bhh1,
         const float* __restrict__ Wih2, const float* __restrict__ Whh2,
         const float* __restrict__ bih2, const float* __restrict__ bhh2,
         const float* __restrict__ Wih3, const float* __restrict__ Whh3,
         const float* __restrict__ bih3, const float* __restrict__ bhh3,
         const float* __restrict__ Wfc,  const float* __restrict__ bfc,
         float* __restrict__ out)
{
    const int tid = threadIdx.x;

    load_wmat(smem + OW1H, Whh1, 8, 32, tid, NT2);
    load_wmat(smem + OW2I, Wih2, 8, 32, tid, NT2);
    load_wmat(smem + OW2H, Whh2, 8, 32, tid, NT2);
    load_wmat(smem + OW3I, Wih3, 8, 32, tid, NT2);
    load_wmat(smem + OW3H, Whh3, 8, 32, tid, NT2);
    {   // FC weights: o = g*32+jj (pad o=95), k = c*4+q
        float* dst = smem + OWFC;
        for (int idx = tid; idx < 3 * 8 * 128; idx += NT2) {
            int q = idx & 3, jj = (idx >> 2) & 31;
            int c = (idx >> 7) % 8, g = idx / (8 * 128);
            int o = g * 32 + jj, k = c * 4 + q;
            dst[idx] = (o < VOC) ? Wfc[o * 32 + k] : 0.f;
        }
    }
    // zero rings (h[-1] = 0 comes from here)
    for (int idx = tid; idx < RING_F2 * 2; idx += NT2)
        smem[ORING + idx] = 0.f;
    __syncthreads();

    const int w = tid >> 5, j = tid & 31;
    const int rb = blockIdx.x * 16;       // 16 rows per block
    float2* const RG = (float2*)(smem + ORING);
    float2* const rh1 = RG + RH1;
    float2* const rxi2 = RG + RXI2;
    float2* const rh2 = RG + RH2;
    float2* const rxi3 = RG + RXI3;
    float2* const rh3 = RG + RH3;

    // role-specific bias packs (bA = first unit's, bB = second unit's)
    ull bA0 = 0, bA1 = 0, bA2 = 0, bB0 = 0, bB1 = 0, bB2 = 0;
    if (w <= 1) {
        bA0 = pk2(bhh1[j]); bA1 = pk2(bhh1[32 + j]); bA2 = pk2(bhh1[64 + j]);
        bB0 = pk2(bih2[j]); bB1 = pk2(bih2[32 + j]); bB2 = pk2(bih2[64 + j]);
    } else if (w == 2) {
        bA0 = pk2(bih2[j]); bA1 = pk2(bih2[32 + j]); bA2 = pk2(bih2[64 + j]);
        bB0 = pk2(bhh2[j]); bB1 = pk2(bhh2[32 + j]); bB2 = pk2(bhh2[64 + j]);
    } else if (w == 3) {
        bA0 = pk2(bhh2[j]); bA1 = pk2(bhh2[32 + j]); bA2 = pk2(bhh2[64 + j]);
    } else if (w == 4) {
        bA0 = pk2(bih3[j]); bA1 = pk2(bih3[32 + j]); bA2 = pk2(bih3[64 + j]);
    } else if (w == 5) {
        bA0 = pk2(bih3[j]); bA1 = pk2(bih3[32 + j]); bA2 = pk2(bih3[64 + j]);
        bB0 = pk2(bhh3[j]); bB1 = pk2(bhh3[32 + j]); bB2 = pk2(bhh3[64 + j]);
    } else if (w == 6) {
        bA0 = pk2(bhh3[j]); bA1 = pk2(bhh3[32 + j]); bA2 = pk2(bhh3[64 + j]);
        bB0 = pk2(bfc[j]);  bB1 = pk2(bfc[32 + j]);
        bB2 = pk2((64 + j < VOC) ? bfc[64 + j] : 0.f);
    } else {
        bA0 = pk2(bfc[j]);  bA1 = pk2(bfc[32 + j]);
        bA2 = pk2((64 + j < VOC) ? bfc[64 + j] : 0.f);
    }

    // L1 warps (w0: pairs 0-3, w1: pairs 4-7) hold xp(t) in registers
    ull curx[4][3];
    if (w <= 1) {
        const int lo1 = w * 4;
#pragma unroll
        for (int p = 0; p < 4; p++) {
            size_t r0 = (size_t)(rb + 2 * (lo1 + p));
#pragma unroll
            for (int g = 0; g < 3; g++) {
                float a = __ldcs(g_xp + (r0 * TT + 0) * 96 + g * 32 + j);
                float b = __ldcs(g_xp + ((r0 + 1) * TT + 0) * 96 + g * 32 + j);
                curx[p][g] = pkf(a, b);
            }
        }
    }

#pragma unroll 1
    for (int tau = 0; tau < TT + 5; tau++) {
        if (w <= 1) {
            const int lo1 = w * 4;          // L1 pairs
            const int lo2 = w * 2;          // L2i pairs (w0:0-1, w1:2-3)
            // prefetch xp(tau+1)
            float nfa[4][3], nfb[4][3];
            if (tau + 1 < TT) {
#pragma unroll
                for (int p = 0; p < 4; p++) {
                    size_t r0 = (size_t)(rb + 2 * (lo1 + p));
#pragma unroll
                    for (int g = 0; g < 3; g++) {
                        nfa[p][g] = __ldcs(g_xp + (r0 * TT + tau + 1) * 96 + g * 32 + j);
                        nfb[p][g] = __ldcs(g_xp + ((r0 + 1) * TT + tau + 1) * 96 + g * 32 + j);
                    }
                }
            }
            // L2i @ t = tau-1
            {
                int t = tau - 1;
                if (t >= 0 && t < TT)
                    stage_iproj<2>(smem + OW2I, j, rh1 + (size_t)(t & 1) * 256,
                                   rxi2, lo2, t, bB0, bB1, bB2);
            }
            // L1 @ t = tau  (recurrence: proj Whh1 over h1[t-1], ew with xp)
            if (tau < TT) {
                const float2* hold_base = rh1 + (size_t)((tau - 1) & 1) * 256;
                ull acc[4][3];
#pragma unroll
                for (int p = 0; p < 4; p++) { acc[p][0] = bA0; acc[p][1] = bA1; acc[p][2] = bA2; }
                proj_multi<4>(smem + OW1H, j, hold_base + lo1 * 32, acc);
                float2* hnew = rh1 + (size_t)(tau & 1) * 256 + lo1 * 32;
#pragma unroll
                for (int p = 0; p < 4; p++) {
                    ull ho = *(const ull*)(hold_base + (lo1 + p) * 32 + j);
                    ull hn = gru_pair(add2(curx[p][0], acc[p][0]),
                                      add2(curx[p][1], acc[p][1]),
                                      curx[p][2], acc[p][2], ho);
                    *(ull*)(hnew + p * 32 + j) = hn;
                }
                if (tau + 1 < TT) {
#pragma unroll
                    for (int p = 0; p < 4; p++)
#pragma unroll
                        for (int g = 0; g < 3; g++)
                            curx[p][g] = pkf(nfa[p][g], nfb[p][g]);
                }
            }
        } else if (w == 2) {
            int t = tau - 1;    // L2i pairs 4-7
            if (t >= 0 && t < TT)
                stage_iproj<4>(smem + OW2I, j, rh1 + (size_t)(t & 1) * 256,
                               rxi2, 4, t, bA0, bA1, bA2);
            t = tau - 2;        // L2h pairs 0-1
            if (t >= 0 && t < TT)
                stage_hrec<2>(smem + OW2H, j, rh2, rxi2, 0, t, bB0, bB1, bB2);
        } else if (w == 3) {
            int t = tau - 2;    // L2h pairs 2-7
            if (t >= 0 && t < TT)
                stage_hrec<6>(smem + OW2H, j, rh2, rxi2, 2, t, bA0, bA1, bA2);
        } else if (w == 4) {
            int t = tau - 3;    // L3i pairs 0-5
            if (t >= 0 && t < TT)
                stage_iproj<6>(smem + OW3I, j, rh2 + (size_t)(t & 1) * 256,
                               rxi3, 0, t, bA0, bA1, bA2);
        } else if (w == 5) {
            int t = tau - 3;    // L3i pairs 6-7
            if (t >= 0 && t < TT)
                stage_iproj<2>(smem + OW3I, j, rh2 + (size_t)(t & 1) * 256,
                               rxi3, 6, t, bA0, bA1, bA2);
            t = tau - 4;        // L3h pairs 0-3
            if (t >= 0 && t < TT)
                stage_hrec<4>(smem + OW3H, j, rh3, rxi3, 0, t, bB0, bB1, bB2);
        } else if (w == 6) {
            int t = tau - 4;    // L3h pairs 4-7
            if (t >= 0 && t < TT)
                stage_hrec<4>(smem + OW3H, j, rh3, rxi3, 4, t, bA0, bA1, bA2);
            t = tau - 5;        // FC pairs 0-1
            if (t >= 0 && t < TT)
                stage_fc<2>(smem + OWFC, j, rh3, 0, t, rb, out, bB0, bB1, bB2);
        } else {
            int t = tau - 5;    // FC pairs 2-7
            if (t >= 0 && t < TT)
                stage_fc<6>(smem + OWFC, j, rh3, 2, t, rb, out, bA0, bA1, bA2);
        }
        __syncthreads();
    }
}

extern "C" void kernel_launch(void* const* d_in, const int* in_sizes, int n_in,
                              void* d_out, int out_size)
{
    const float* x    = (const float*)d_in[0];
    const float* Wih1 = (const float*)d_in[1];
    const float* Whh1 = (const float*)d_in[2];
    const float* bih1 = (const float*)d_in[3];
    const float* bhh1 = (const float*)d_in[4];
    const float* Wih2 = (const float*)d_in[5];
    const float* Whh2 = (const float*)d_in[6];
    const float* bih2 = (const float*)d_in[7];
    const float* bhh2 = (const float*)d_in[8];
    const float* Wih3 = (const float*)d_in[9];
    const float* Whh3 = (const float*)d_in[10];
    const float* bih3 = (const float*)d_in[11];
    const float* bhh3 = (const float*)d_in[12];
    const float* Wfc  = (const float*)d_in[13];
    const float* bfc  = (const float*)d_in[14];
    float* out = (float*)d_out;

    cudaFuncSetAttribute(gru_xproj, cudaFuncAttributeMaxDynamicSharedMemorySize,
                         K1_SMEM_BYTES);
    cudaFuncSetAttribute(gru_scan, cudaFuncAttributeMaxDynamicSharedMemorySize,
                         SC_SMEM_BYTES);

    gru_xproj<<<K1_NB, K1_NT, K1_SMEM_BYTES>>>(x, Wih1, bih1);
    gru_scan<<<NB2, NT2, SC_SMEM_BYTES>>>(Whh1, bhh1,
                                          Wih2, Whh2, bih2, bhh2,
                                          Wih3, Whh3, bih3, bhh3,
                                          Wfc, bfc, out);
}

// round 8
// speedup vs baseline: 1.5310x; 1.5310x over previous
#include <cuda_runtime.h>
#include <cstdint>

using ull = unsigned long long;

#define VOC 95
#define TT  256
#define NB  128
#define NT  256    // 8 warps

// ---- SMEM layout (float offsets) ----
#define OW1I 0        // Wih1 [3][24][32][4] = 9216
#define OW1H 9216     // [3][8][32][4] = 3072 each below
#define OW2I 12288
#define OW2H 15360
#define OW3I 18432
#define OW3H 21504
#define OWFC 24576
#define ORB  27648    // float2 ring region base
// float2 offsets within ring region:
#define XSTG 0        // x stage   [2][8 pairs][96]
#define XP   1536     // xp ring   [2][8 pairs][96]
#define H3   3072     // h3 ring   [2][8 pairs][32]
#define HS   3584     // h1/h2     [8 pairs][2][32]
#define RING_F2 4096
#define SMEM_FLOATS (ORB + RING_F2 * 2)   // 35840
#define SMEM_BYTES  (SMEM_FLOATS * 4)     // 143360

extern __shared__ float smem[];

// ---------- packed fp32x2 helpers ----------
__device__ __forceinline__ ull pk2(float w) {
    ull d; unsigned r = __float_as_uint(w);
    asm("mov.b64 %0, {%1,%1};" : "=l"(d) : "r"(r));
    return d;
}
__device__ __forceinline__ ull pkf(float a, float b) {
    ull d;
    asm("mov.b64 %0, {%1,%2};" : "=l"(d)
        : "r"(__float_as_uint(a)), "r"(__float_as_uint(b)));
    return d;
}
__device__ __forceinline__ float2 up2(ull v) {
    unsigned lo, hi;
    asm("mov.b64 {%0,%1}, %2;" : "=r"(lo), "=r"(hi) : "l"(v));
    return make_float2(__uint_as_float(lo), __uint_as_float(hi));
}
__device__ __forceinline__ void fma2(ull& d, ull a, ull b) {
    asm("fma.rn.f32x2 %0, %1, %2, %0;" : "+l"(d) : "l"(a), "l"(b));
}
__device__ __forceinline__ ull add2(ull a, ull b) {
    ull d; asm("add.rn.f32x2 %0, %1, %2;" : "=l"(d) : "l"(a), "l"(b));
    return d;
}

// ---------- activations ----------
__device__ __forceinline__ float tanhap(float v) {
    float r; asm("tanh.approx.f32 %0, %1;" : "=f"(r) : "f"(v)); return r;
}
__device__ __forceinline__ float fsig(float v) {
    return fmaf(tanhap(0.5f * v), 0.5f, 0.5f);
}

// GRU elementwise for one packed pair
__device__ __forceinline__ ull gru_pair(ull aR, ull aZ, ull aNx, ull aNh, ull h)
{
    float2 r2 = up2(aR), z2 = up2(aZ), nx = up2(aNx), nh = up2(aNh), hh = up2(h);
    float r0 = fsig(r2.x), r1 = fsig(r2.y);
    float z0 = fsig(z2.x), z1 = fsig(z2.y);
    float n0 = tanhap(nx.x + r0 * nh.x);
    float n1 = tanhap(nx.y + r1 * nh.y);
    float h0 = n0 + z0 * (hh.x - n0);
    float h1 = n1 + z1 * (hh.y - n1);
    return pkf(h0, h1);
}

// 3-gate projection, 8 chunks, P pairs with input stride STR (float2 units)
template<int P, int STR>
__device__ __forceinline__ void projS(const float* __restrict__ W, int j,
                                      const float2* __restrict__ in,
                                      ull (&acc)[P][3])
{
#pragma unroll
    for (int c = 0; c < 8; c++) {
        float4 wA = *(const float4*)(W + ((0 * 8 + c) * 32 + j) * 4);
        float4 wB = *(const float4*)(W + ((1 * 8 + c) * 32 + j) * 4);
        float4 wC = *(const float4*)(W + ((2 * 8 + c) * 32 + j) * 4);
        ull a0 = pk2(wA.x), a1 = pk2(wA.y), a2 = pk2(wA.z), a3 = pk2(wA.w);
        ull b0 = pk2(wB.x), b1 = pk2(wB.y), b2 = pk2(wB.z), b3 = pk2(wB.w);
        ull c0 = pk2(wC.x), c1 = pk2(wC.y), c2 = pk2(wC.z), c3 = pk2(wC.w);
#pragma unroll
        for (int p = 0; p < P; p++) {
            ulonglong2 x01 = *(const ulonglong2*)(in + p * STR + 4 * c);
            ulonglong2 x23 = *(const ulonglong2*)(in + p * STR + 4 * c + 2);
            fma2(acc[p][0], x01.x, a0); fma2(acc[p][0], x01.y, a1);
            fma2(acc[p][0], x23.x, a2); fma2(acc[p][0], x23.y, a3);
            fma2(acc[p][1], x01.x, b0); fma2(acc[p][1], x01.y, b1);
            fma2(acc[p][1], x23.x, b2); fma2(acc[p][1], x23.y, b3);
            fma2(acc[p][2], x01.x, c0); fma2(acc[p][2], x01.y, c1);
            fma2(acc[p][2], x23.x, c2); fma2(acc[p][2], x23.y, c3);
        }
    }
}

// 3-gate projection, 24 chunks (Wih1), P pairs with stride 96
template<int P>
__device__ __forceinline__ void projX(const float* __restrict__ W, int j,
                                      const float2* __restrict__ in,
                                      ull (&acc)[P][3])
{
#pragma unroll 4
    for (int c = 0; c < 24; c++) {
        float4 wA = *(const float4*)(W + ((0 * 24 + c) * 32 + j) * 4);
        float4 wB = *(const float4*)(W + ((1 * 24 + c) * 32 + j) * 4);
        float4 wC = *(const float4*)(W + ((2 * 24 + c) * 32 + j) * 4);
        ull a0 = pk2(wA.x), a1 = pk2(wA.y), a2 = pk2(wA.z), a3 = pk2(wA.w);
        ull b0 = pk2(wB.x), b1 = pk2(wB.y), b2 = pk2(wB.z), b3 = pk2(wB.w);
        ull c0 = pk2(wC.x), c1 = pk2(wC.y), c2 = pk2(wC.z), c3 = pk2(wC.w);
#pragma unroll
        for (int p = 0; p < P; p++) {
            ulonglong2 x01 = *(const ulonglong2*)(in + p * 96 + 4 * c);
            ulonglong2 x23 = *(const ulonglong2*)(in + p * 96 + 4 * c + 2);
            fma2(acc[p][0], x01.x, a0); fma2(acc[p][0], x01.y, a1);
            fma2(acc[p][0], x23.x, a2); fma2(acc[p][0], x23.y, a3);
            fma2(acc[p][1], x01.x, b0); fma2(acc[p][1], x01.y, b1);
            fma2(acc[p][1], x23.x, b2); fma2(acc[p][1], x23.y, b3);
            fma2(acc[p][2], x01.x, c0); fma2(acc[p][2], x01.y, c1);
            fma2(acc[p][2], x23.x, c2); fma2(acc[p][2], x23.y, c3);
        }
    }
}

// GMEM weight [3*32, isz] -> SMEM [g][c][lane][4]
__device__ __forceinline__ void load_wmat(float* dst, const float* __restrict__ src,
                                          int C, int isz, int tid)
{
    int n = 3 * C * 128;
    for (int idx = tid; idx < n; idx += NT) {
        int q = idx & 3, jj = (idx >> 2) & 31;
        int c = (idx >> 7) % C, g = idx / (C * 128);
        int i = c * 4 + q;
        dst[idx] = (i < isz) ? src[(g * 32 + jj) * isz + i] : 0.f;
    }
}

// S-warp tick: full L1h->L2->L3 chain for NP pairs starting at pair lo
template<int NP>
__device__ __forceinline__ void s_tick(float2* RB, int lo, int j, int t,
                                       const ull (&bs)[5][3])
{
    float2* hsb = (float2*)(RB + HS);
    const float2* xps = RB + XP + (size_t)(t & 1) * 768;

    // ---- L1: hidden proj + ew with xp ----
    ull acc[NP][3];
#pragma unroll
    for (int p = 0; p < NP; p++) { acc[p][0] = bs[0][0]; acc[p][1] = bs[0][1]; acc[p][2] = bs[0][2]; }
    projS<NP, 64>(smem + OW1H, j, hsb + lo * 64, acc);
    ull hold[NP];
#pragma unroll
    for (int p = 0; p < NP; p++) hold[p] = *(const ull*)(hsb + (lo + p) * 64 + j);
    __syncwarp();
#pragma unroll
    for (int p = 0; p < NP; p++) {
        ull xr = *(const ull*)(xps + (lo + p) * 96 + j);
        ull xz = *(const ull*)(xps + (lo + p) * 96 + 32 + j);
        ull xn = *(const ull*)(xps + (lo + p) * 96 + 64 + j);
        ull hn = gru_pair(add2(xr, acc[p][0]), add2(xz, acc[p][1]),
                          xn, acc[p][2], hold[p]);
        *(ull*)(hsb + (lo + p) * 64 + j) = hn;
    }
    __syncwarp();

    // ---- L2: input proj (regs) + hidden proj + ew ----
    ull xi[NP][3];
#pragma unroll
    for (int p = 0; p < NP; p++) { xi[p][0] = bs[1][0]; xi[p][1] = bs[1][1]; xi[p][2] = bs[1][2]; }
    projS<NP, 64>(smem + OW2I, j, hsb + lo * 64, xi);
#pragma unroll
    for (int p = 0; p < NP; p++) { acc[p][0] = bs[2][0]; acc[p][1] = bs[2][1]; acc[p][2] = bs[2][2]; }
    projS<NP, 64>(smem + OW2H, j, hsb + lo * 64 + 32, acc);
#pragma unroll
    for (int p = 0; p < NP; p++) hold[p] = *(const ull*)(hsb + (lo + p) * 64 + 32 + j);
    __syncwarp();
#pragma unroll
    for (int p = 0; p < NP; p++) {
        ull hn = gru_pair(add2(xi[p][0], acc[p][0]), add2(xi[p][1], acc[p][1]),
                          xi[p][2], acc[p][2], hold[p]);
        *(ull*)(hsb + (lo + p) * 64 + 32 + j) = hn;
    }
    __syncwarp();

    // ---- L3: input proj (regs) + hidden proj over h3 ring + ew ----
#pragma unroll
    for (int p = 0; p < NP; p++) { xi[p][0] = bs[3][0]; xi[p][1] = bs[3][1]; xi[p][2] = bs[3][2]; }
    projS<NP, 64>(smem + OW3I, j, hsb + lo * 64 + 32, xi);
    const float2* h3o = RB + H3 + (size_t)((t - 1) & 1) * 256;
#pragma unroll
    for (int p = 0; p < NP; p++) { acc[p][0] = bs[4][0]; acc[p][1] = bs[4][1]; acc[p][2] = bs[4][2]; }
    projS<NP, 32>(smem + OW3H, j, h3o + lo * 32, acc);
    float2* h3n = RB + H3 + (size_t)(t & 1) * 256;
#pragma unroll
    for (int p = 0; p < NP; p++) {
        ull ho = *(const ull*)(h3o + (lo + p) * 32 + j);
        ull hn = gru_pair(add2(xi[p][0], acc[p][0]), add2(xi[p][1], acc[p][1]),
                          xi[p][2], acc[p][2], ho);
        *(ull*)(h3n + (lo + p) * 32 + j) = hn;
    }
}

__global__ void __launch_bounds__(NT, 1)
gru_all(const float* __restrict__ x,
        const float* __restrict__ Wih1, const float* __restrict__ Whh1,
        const float* __restrict__ bih1, const float* __restrict__ bhh1,
        const float* __restrict__ Wih2, const float* __restrict__ Whh2,
        const float* __restrict__ bih2, const float* __restrict__ bhh2,
        const float* __restrict__ Wih3, const float* __restrict__ Whh3,
        const float* __restrict__ bih3, const float* __restrict__ bhh3,
        const float* __restrict__ Wfc,  const float* __restrict__ bfc,
        float* __restrict__ out)
{
    const int tid = threadIdx.x;

    load_wmat(smem + OW1I, Wih1, 24, VOC, tid);
    load_wmat(smem + OW1H, Whh1, 8, 32, tid);
    load_wmat(smem + OW2I, Wih2, 8, 32, tid);
    load_wmat(smem + OW2H, Whh2, 8, 32, tid);
    load_wmat(smem + OW3I, Wih3, 8, 32, tid);
    load_wmat(smem + OW3H, Whh3, 8, 32, tid);
    {   // FC weights permute
        float* dst = smem + OWFC;
        for (int idx = tid; idx < 3 * 8 * 128; idx += NT) {
            int q = idx & 3, jj = (idx >> 2) & 31;
            int c = (idx >> 7) % 8, g = idx / (8 * 128);
            int o = g * 32 + jj, k = c * 4 + q;
            dst[idx] = (o < VOC) ? Wfc[o * 32 + k] : 0.f;
        }
    }
    // zero ring region (h(-1)=0, x-stage pad stays 0)
    for (int idx = tid; idx < RING_F2 * 2; idx += NT)
        smem[ORB + idx] = 0.f;
    __syncthreads();

    const int w = tid >> 5, j = tid & 31;
    const int rb = blockIdx.x * 16;
    float2* const RB = (float2*)(smem + ORB);

    if (w < 2) {
        // ================= P role: xp producer, 4 pairs =================
        const int pl0 = w * 4;
        const ull bR = pk2(bih1[j]), bZ = pk2(bih1[32 + j]), bN = pk2(bih1[64 + j]);

        // prologue: stage x(0) into slot 0
#pragma unroll
        for (int p = 0; p < 4; p++) {
            size_t r0 = (size_t)(rb + 2 * (pl0 + p));
#pragma unroll
            for (int k = 0; k < 3; k++) {
                int i = j + 32 * k;
                if (i < VOC) {
                    float a = __ldcs(x + (r0 * TT + 0) * VOC + i);
                    float b = __ldcs(x + ((r0 + 1) * TT + 0) * VOC + i);
                    RB[XSTG + (pl0 + p) * 96 + i] = make_float2(a, b);
                }
            }
        }
        __syncwarp();

#pragma unroll 1
        for (int tau = 0; tau < TT + 2; tau++) {
            float pa[4][3], pb[4][3];
            if (tau + 1 < TT) {
#pragma unroll
                for (int p = 0; p < 4; p++) {
                    size_t r0 = (size_t)(rb + 2 * (pl0 + p));
#pragma unroll
                    for (int k = 0; k < 3; k++) {
                        int i = j + 32 * k;
                        if (i < VOC) {
                            pa[p][k] = __ldcs(x + (r0 * TT + tau + 1) * VOC + i);
                            pb[p][k] = __ldcs(x + ((r0 + 1) * TT + tau + 1) * VOC + i);
                        }
                    }
                }
            }
            if (tau < TT) {
                ull acc[4][3];
#pragma unroll
                for (int p = 0; p < 4; p++) { acc[p][0] = bR; acc[p][1] = bZ; acc[p][2] = bN; }
                projX<4>(smem + OW1I, j,
                         RB + XSTG + (size_t)(tau & 1) * 768 + pl0 * 96, acc);
                float2* xo = RB + XP + (size_t)(tau & 1) * 768;
#pragma unroll
                for (int p = 0; p < 4; p++)
#pragma unroll
                    for (int g = 0; g < 3; g++)
                        *(ull*)(xo + (pl0 + p) * 96 + g * 32 + j) = acc[p][g];
            }
            if (tau + 1 < TT) {
                float2* xs = RB + XSTG + (size_t)((tau + 1) & 1) * 768;
#pragma unroll
                for (int p = 0; p < 4; p++)
#pragma unroll
                    for (int k = 0; k < 3; k++) {
                        int i = j + 32 * k;
                        if (i < VOC)
                            xs[(pl0 + p) * 96 + i] = make_float2(pa[p][k], pb[p][k]);
                    }
            }
            __syncthreads();
        }
    } else if (w < 6) {
        // ================= S role: recurrence chain =================
        // pair counts (1,1,3,3) for FMA balance: w4,w5 -> 1 pair; w2,w3 -> 3 pairs
        int lo, np;
        if (w == 4)      { lo = 0; np = 1; }
        else if (w == 5) { lo = 1; np = 1; }
        else if (w == 2) { lo = 2; np = 3; }
        else             { lo = 5; np = 3; }

        ull bs[5][3];
        bs[0][0] = pk2(bhh1[j]); bs[0][1] = pk2(bhh1[32 + j]); bs[0][2] = pk2(bhh1[64 + j]);
        bs[1][0] = pk2(bih2[j]); bs[1][1] = pk2(bih2[32 + j]); bs[1][2] = pk2(bih2[64 + j]);
        bs[2][0] = pk2(bhh2[j]); bs[2][1] = pk2(bhh2[32 + j]); bs[2][2] = pk2(bhh2[64 + j]);
        bs[3][0] = pk2(bih3[j]); bs[3][1] = pk2(bih3[32 + j]); bs[3][2] = pk2(bih3[64 + j]);
        bs[4][0] = pk2(bhh3[j]); bs[4][1] = pk2(bhh3[32 + j]); bs[4][2] = pk2(bhh3[64 + j]);

#pragma unroll 1
        for (int tau = 0; tau < TT + 2; tau++) {
            int t = tau - 1;
            if (t >= 0 && t < TT) {
                if (np == 1) s_tick<1>(RB, lo, j, t, bs);
                else         s_tick<3>(RB, lo, j, t, bs);
            }
            __syncthreads();
        }
    } else {
        // ================= F role: FC head at t-1 =================
        const int flo = (w == 6) ? 0 : 4;
        ull bf0 = pk2(bfc[j]), bf1 = pk2(bfc[32 + j]);
        ull bf2 = pk2((64 + j < VOC) ? bfc[64 + j] : 0.f);

#pragma unroll 1
        for (int tau = 0; tau < TT + 2; tau++) {
            int t = tau - 2;
            if (t >= 0 && t < TT) {
                const float2* h3s = RB + H3 + (size_t)(t & 1) * 256;
                ull acc[4][3];
#pragma unroll
                for (int p = 0; p < 4; p++) { acc[p][0] = bf0; acc[p][1] = bf1; acc[p][2] = bf2; }
                projS<4, 32>(smem + OWFC, j, h3s + flo * 32, acc);
#pragma unroll
                for (int p = 0; p < 4; p++) {
                    size_t r0 = (size_t)(rb + 2 * (flo + p));
                    size_t base0 = (r0 * TT + t) * VOC;
                    size_t base1 = base0 + (size_t)TT * VOC;
                    float2 v;
                    v = up2(acc[p][0]); __stcs(out + base0 + j, v.x);      __stcs(out + base1 + j, v.y);
                    v = up2(acc[p][1]); __stcs(out + base0 + 32 + j, v.x); __stcs(out + base1 + 32 + j, v.y);
                    if (64 + j < VOC) {
                        v = up2(acc[p][2]); __stcs(out + base0 + 64 + j, v.x); __stcs(out + base1 + 64 + j, v.y);
                    }
                }
            }
            __syncthreads();
        }
    }
}

extern "C" void kernel_launch(void* const* d_in, const int* in_sizes, int n_in,
                              void* d_out, int out_size)
{
    const float* x    = (const float*)d_in[0];
    const float* Wih1 = (const float*)d_in[1];
    const float* Whh1 = (const float*)d_in[2];
    const float* bih1 = (const float*)d_in[3];
    const float* bhh1 = (const float*)d_in[4];
    const float* Wih2 = (const float*)d_in[5];
    const float* Whh2 = (const float*)d_in[6];
    const float* bih2 = (const float*)d_in[7];
    const float* bhh2 = (const float*)d_in[8];
    const float* Wih3 = (const float*)d_in[9];
    const float* Whh3 = (const float*)d_in[10];
    const float* bih3 = (const float*)d_in[11];
    const float* bhh3 = (const float*)d_in[12];
    const float* Wfc  = (const float*)d_in[13];
    const float* bfc  = (const float*)d_in[14];
    float* out = (float*)d_out;

    cudaFuncSetAttribute(gru_all, cudaFuncAttributeMaxDynamicSharedMemorySize,
                         SMEM_BYTES);
    gru_all<<<NB, NT, SMEM_BYTES>>>(x, Wih1, Whh1, bih1, bhh1,
                                    Wih2, Whh2, bih2, bhh2,
                                    Wih3, Whh3, bih3, bhh3,
                                    Wfc, bfc, out);
}

// round 9
// speedup vs baseline: 1.8891x; 1.2339x over previous
#include <cuda_runtime.h>
#include <cuda_fp16.h>
#include <cstdint>

using ull = unsigned long long;

#define VOC 95
#define TT  256
#define BB  2048

// ---------------- scratch: xp = x @ Wih1^T + bih1  [B*T, 96] ----------------
__device__ float g_xp[(size_t)BB * TT * 96];

// ---------- packed fp32x2 helpers ----------
__device__ __forceinline__ ull pk2(float w) {
    ull d; unsigned r = __float_as_uint(w);
    asm("mov.b64 %0, {%1,%1};" : "=l"(d) : "r"(r));
    return d;
}
__device__ __forceinline__ ull pkf(float a, float b) {
    ull d;
    asm("mov.b64 %0, {%1,%2};" : "=l"(d)
        : "r"(__float_as_uint(a)), "r"(__float_as_uint(b)));
    return d;
}
__device__ __forceinline__ float2 up2(ull v) {
    unsigned lo, hi;
    asm("mov.b64 {%0,%1}, %2;" : "=r"(lo), "=r"(hi) : "l"(v));
    return make_float2(__uint_as_float(lo), __uint_as_float(hi));
}
__device__ __forceinline__ void fma2(ull& d, ull a, ull b) {
    asm("fma.rn.f32x2 %0, %1, %2, %0;" : "+l"(d) : "l"(a), "l"(b));
}
__device__ __forceinline__ ull add2(ull a, ull b) {
    ull d; asm("add.rn.f32x2 %0, %1, %2;" : "=l"(d) : "l"(a), "l"(b));
    return d;
}

// ---------- activations (MUFU tanh.approx) ----------
__device__ __forceinline__ float tanhap(float v) {
    float r; asm("tanh.approx.f32 %0, %1;" : "=f"(r) : "f"(v)); return r;
}
__device__ __forceinline__ float fsig(float v) {
    return fmaf(tanhap(0.5f * v), 0.5f, 0.5f);
}

extern __shared__ float smem[];

// GMEM weight [3*32, isz] -> SMEM fp32 [g][c][lane][4] (i >= isz zero-padded)
__device__ __forceinline__ void load_wmat(float* dst, const float* __restrict__ src,
                                          int C, int isz, int tid, int nthr)
{
    int n = 3 * C * 128;
    for (int idx = tid; idx < n; idx += nthr) {
        int q = idx & 3, jj = (idx >> 2) & 31;
        int c = (idx >> 7) % C, g = idx / (C * 128);
        int i = c * 4 + q;
        dst[idx] = (i < isz) ? src[(g * 32 + jj) * isz + i] : 0.f;
    }
}

// GMEM weight [3*32, 32] -> SMEM fp16 [g][c][lane][4]  (C=8, isz=32)
__device__ __forceinline__ void load_wmat_h(__half* dst, const float* __restrict__ src,
                                            int tid, int nthr)
{
    const int n = 3 * 8 * 128;
    for (int idx = tid; idx < n; idx += nthr) {
        int q = idx & 3, jj = (idx >> 2) & 31;
        int c = (idx >> 7) % 8, g = idx / (8 * 128);
        int i = c * 4 + q;
        dst[idx] = __float2half_rn(src[(g * 32 + jj) * 32 + i]);
    }
}

// ============================================================================
// Kernel 1: xp[r][96] = x[r][95] @ Wih1^T + bih1   (unchanged from R6)
// ============================================================================
#define K1_NB   256
#define K1_NT   256
#define K1_XS   9216
#define K1_SMEM_FLOATS (9216 + 8 * 8 * 96 * 2)
#define K1_SMEM_BYTES  (K1_SMEM_FLOATS * 4)

__global__ void __launch_bounds__(K1_NT, 2)
gru_xproj(const float* __restrict__ x,
          const float* __restrict__ Wih1,
          const float* __restrict__ bih1)
{
    const int tid = threadIdx.x;
    load_wmat(smem, Wih1, 24, VOC, tid, K1_NT);
    __syncthreads();

    const int w = tid >> 5, j = tid & 31;
    float2* xsw = (float2*)(smem + K1_XS) + (size_t)w * (8 * 96);

    const ull bR = pk2(bih1[j]), bZ = pk2(bih1[32 + j]), bN = pk2(bih1[64 + j]);
    const size_t pairBase = ((size_t)blockIdx.x * 8 + w) * 128;

#pragma unroll 1
    for (int it = 0; it < 16; it++) {
        const size_t p0 = pairBase + (size_t)it * 8;

#pragma unroll
        for (int p = 0; p < 8; p++) {
            size_t r0 = (p0 + p) * 2, r1 = r0 + 1;
#pragma unroll
            for (int k = 0; k < 3; k++) {
                int i = j + 32 * k;
                float a = 0.f, b = 0.f;
                if (i < VOC) {
                    a = __ldcs(x + r0 * VOC + i);
                    b = __ldcs(x + r1 * VOC + i);
                }
                xsw[p * 96 + i] = make_float2(a, b);
            }
        }
        __syncwarp();

        ull acc[8][3];
#pragma unroll
        for (int p = 0; p < 8; p++) { acc[p][0] = bR; acc[p][1] = bZ; acc[p][2] = bN; }

#pragma unroll 2
        for (int c = 0; c < 24; c++) {
            float4 wA = *(const float4*)(smem + ((0 * 24 + c) * 32 + j) * 4);
            float4 wB = *(const float4*)(smem + ((1 * 24 + c) * 32 + j) * 4);
            float4 wC = *(const float4*)(smem + ((2 * 24 + c) * 32 + j) * 4);
            ull a0 = pk2(wA.x), a1 = pk2(wA.y), a2 = pk2(wA.z), a3 = pk2(wA.w);
            ull b0 = pk2(wB.x), b1 = pk2(wB.y), b2 = pk2(wB.z), b3 = pk2(wB.w);
            ull c0 = pk2(wC.x), c1 = pk2(wC.y), c2 = pk2(wC.z), c3 = pk2(wC.w);
#pragma unroll
            for (int p = 0; p < 8; p++) {
                ulonglong2 x01 = *(const ulonglong2*)(xsw + p * 96 + 4 * c);
                ulonglong2 x23 = *(const ulonglong2*)(xsw + p * 96 + 4 * c + 2);
                fma2(acc[p][0], x01.x, a0); fma2(acc[p][0], x01.y, a1);
                fma2(acc[p][0], x23.x, a2); fma2(acc[p][0], x23.y, a3);
                fma2(acc[p][1], x01.x, b0); fma2(acc[p][1], x01.y, b1);
                fma2(acc[p][1], x23.x, b2); fma2(acc[p][1], x23.y, b3);
                fma2(acc[p][2], x01.x, c0); fma2(acc[p][2], x01.y, c1);
                fma2(acc[p][2], x23.x, c2); fma2(acc[p][2], x23.y, c3);
            }
        }

#pragma unroll
        for (int p = 0; p < 8; p++) {
            size_t r0 = (p0 + p) * 2, r1 = r0 + 1;
#pragma unroll
            for (int g = 0; g < 3; g++) {
                float2 v = up2(acc[p][g]);
                g_xp[r0 * 96 + g * 32 + j] = v.x;
                g_xp[r1 * 96 + g * 32 + j] = v.y;
            }
        }
        __syncwarp();
    }
}

// ============================================================================
// Kernel 2: fused scan (R6 structure) with fp16 weights for the 5 recurrent/
// input matrices; WFC stays fp32.
// ============================================================================
#define NW  4
#define NT2 (NW * 32)
#define NB  128

// half-unit offsets within the fp16 weight region (each matrix = 3072 halves)
#define HW1H 0
#define HW2I 3072
#define HW2H 6144
#define HW3I 9216
#define HW3H 12288
#define HALF_REGION_FLOATS 7680      // 15360 halves = 30720 B = 7680 floats
// float offsets
#define OWFC 7680                     // 3072 floats
#define OFF_HS 10752                  // float2 hs[4 w][3 layer][2 pair][32] = 1536 floats
#define K2_SMEM_FLOATS (10752 + 1536)
#define K2_SMEM_BYTES  (K2_SMEM_FLOATS * 4)

// unpack 4 fp16 weights (uint2) into two float2
__device__ __forceinline__ void h4tof(uint2 w, float2& lo, float2& hi) {
    lo = __half22float2(*reinterpret_cast<__half2*>(&w.x));
    hi = __half22float2(*reinterpret_cast<__half2*>(&w.y));
}

// ---------- 3-gate projection, 8 chunks, fp16 weights, 2 packed pairs ----
__device__ __forceinline__ void proj3h(const __half* __restrict__ W, int j,
                                       const float2* __restrict__ in0,
                                       const float2* __restrict__ in1,
                                       ull& aA0, ull& aB0, ull& aC0,
                                       ull& aA1, ull& aB1, ull& aC1)
{
#pragma unroll
    for (int c = 0; c < 8; c++) {
        uint2 hA = *(const uint2*)(W + ((0 * 8 + c) * 32 + j) * 4);
        uint2 hB = *(const uint2*)(W + ((1 * 8 + c) * 32 + j) * 4);
        uint2 hC = *(const uint2*)(W + ((2 * 8 + c) * 32 + j) * 4);
        ulonglong2 x01 = *(const ulonglong2*)(in0 + 4 * c);
        ulonglong2 x23 = *(const ulonglong2*)(in0 + 4 * c + 2);
        ulonglong2 y01 = *(const ulonglong2*)(in1 + 4 * c);
        ulonglong2 y23 = *(const ulonglong2*)(in1 + 4 * c + 2);
        float2 A01, A23, B01, B23, C01, C23;
        h4tof(hA, A01, A23);
        h4tof(hB, B01, B23);
        h4tof(hC, C01, C23);
        ull w;
        w = pk2(A01.x); fma2(aA0, x01.x, w); fma2(aA1, y01.x, w);
        w = pk2(A01.y); fma2(aA0, x01.y, w); fma2(aA1, y01.y, w);
        w = pk2(A23.x); fma2(aA0, x23.x, w); fma2(aA1, y23.x, w);
        w = pk2(A23.y); fma2(aA0, x23.y, w); fma2(aA1, y23.y, w);
        w = pk2(B01.x); fma2(aB0, x01.x, w); fma2(aB1, y01.x, w);
        w = pk2(B01.y); fma2(aB0, x01.y, w); fma2(aB1, y01.y, w);
        w = pk2(B23.x); fma2(aB0, x23.x, w); fma2(aB1, y23.x, w);
        w = pk2(B23.y); fma2(aB0, x23.y, w); fma2(aB1, y23.y, w);
        w = pk2(C01.x); fma2(aC0, x01.x, w); fma2(aC1, y01.x, w);
        w = pk2(C01.y); fma2(aC0, x01.y, w); fma2(aC1, y01.y, w);
        w = pk2(C23.x); fma2(aC0, x23.x, w); fma2(aC1, y23.x, w);
        w = pk2(C23.y); fma2(aC0, x23.y, w); fma2(aC1, y23.y, w);
    }
}

// ---------- 3-gate projection, 8 chunks, fp32 weights (FC head) ----
__device__ __forceinline__ void proj3f(const float* __restrict__ W, int j,
                                       const float2* __restrict__ in0,
                                       const float2* __restrict__ in1,
                                       ull& aA0, ull& aB0, ull& aC0,
                                       ull& aA1, ull& aB1, ull& aC1)
{
#pragma unroll
    for (int c = 0; c < 8; c++) {
        float4 wA = *(const float4*)(W + ((0 * 8 + c) * 32 + j) * 4);
        float4 wB = *(const float4*)(W + ((1 * 8 + c) * 32 + j) * 4);
        float4 wC = *(const float4*)(W + ((2 * 8 + c) * 32 + j) * 4);
        ulonglong2 x01 = *(const ulonglong2*)(in0 + 4 * c);
        ulonglong2 x23 = *(const ulonglong2*)(in0 + 4 * c + 2);
        ulonglong2 y01 = *(const ulonglong2*)(in1 + 4 * c);
        ulonglong2 y23 = *(const ulonglong2*)(in1 + 4 * c + 2);
        ull w;
        w = pk2(wA.x); fma2(aA0, x01.x, w); fma2(aA1, y01.x, w);
        w = pk2(wA.y); fma2(aA0, x01.y, w); fma2(aA1, y01.y, w);
        w = pk2(wA.z); fma2(aA0, x23.x, w); fma2(aA1, y23.x, w);
        w = pk2(wA.w); fma2(aA0, x23.y, w); fma2(aA1, y23.y, w);
        w = pk2(wB.x); fma2(aB0, x01.x, w); fma2(aB1, y01.x, w);
        w = pk2(wB.y); fma2(aB0, x01.y, w); fma2(aB1, y01.y, w);
        w = pk2(wB.z); fma2(aB0, x23.x, w); fma2(aB1, y23.x, w);
        w = pk2(wB.w); fma2(aB0, x23.y, w); fma2(aB1, y23.y, w);
        w = pk2(wC.x); fma2(aC0, x01.x, w); fma2(aC1, y01.x, w);
        w = pk2(wC.y); fma2(aC0, x01.y, w); fma2(aC1, y01.y, w);
        w = pk2(wC.z); fma2(aC0, x23.x, w); fma2(aC1, y23.x, w);
        w = pk2(wC.w); fma2(aC0, x23.y, w); fma2(aC1, y23.y, w);
    }
}

// ---------- GRU elementwise for one packed row-pair ----------
__device__ __forceinline__ ull gru_pair(ull aR, ull aZ, ull aNx, ull aNh, ull h)
{
    float2 r2 = up2(aR), z2 = up2(aZ), nx = up2(aNx), nh = up2(aNh), hh = up2(h);
    float r0 = fsig(r2.x), r1 = fsig(r2.y);
    float z0 = fsig(z2.x), z1 = fsig(z2.y);
    float n0 = tanhap(nx.x + r0 * nh.x);
    float n1 = tanhap(nx.y + r1 * nh.y);
    float h0 = n0 + z0 * (hh.x - n0);
    float h1 = n1 + z1 * (hh.y - n1);
    return pkf(h0, h1);
}

// One GRU layer step (layers 2,3): fp16 weights, input from SMEM, 2 pairs.
__device__ __forceinline__ void layer_step_h(const __half* __restrict__ Wi,
                                             const __half* __restrict__ Wh,
                                             const float2* __restrict__ in0,
                                             const float2* __restrict__ in1,
                                             float2* hbuf, int j,
                                             ull biR, ull biZ, ull biN,
                                             ull bhR, ull bhZ, ull bhN)
{
    ull xR0 = biR, xZ0 = biZ, xN0 = biN, xR1 = biR, xZ1 = biZ, xN1 = biN;
    proj3h(Wi, j, in0, in1, xR0, xZ0, xN0, xR1, xZ1, xN1);
    ull hR0 = bhR, hZ0 = bhZ, hN0 = bhN, hR1 = bhR, hZ1 = bhZ, hN1 = bhN;
    proj3h(Wh, j, hbuf, hbuf + 32, hR0, hZ0, hN0, hR1, hZ1, hN1);
    ull h0 = *(const ull*)(hbuf + j);
    ull h1 = *(const ull*)(hbuf + 32 + j);
    __syncwarp();
    ull n0 = gru_pair(add2(xR0, hR0), add2(xZ0, hZ0), xN0, hN0, h0);
    ull n1 = gru_pair(add2(xR1, hR1), add2(xZ1, hZ1), xN1, hN1, h1);
    *(ull*)(hbuf + j) = n0;
    *(ull*)(hbuf + 32 + j) = n1;
    __syncwarp();
}

__global__ void __launch_bounds__(NT2, 1)
gru_scan(const float* __restrict__ Whh1, const float* __restrict__ bhh1,
         const float* __restrict__ Wih2, const float* __restrict__ Whh2,
         const float* __restrict__ bih2, const float* __restrict__ bhh2,
         const float* __restrict__ Wih3, const float* __restrict__ Whh3,
         const float* __restrict__ bih3, const float* __restrict__ bhh3,
         const float* __restrict__ Wfc,  const float* __restrict__ bfc,
         float* __restrict__ out)
{
    const int tid = threadIdx.x;
    __half* const smem_h = (__half*)smem;

    load_wmat_h(smem_h + HW1H, Whh1, tid, NT2);
    load_wmat_h(smem_h + HW2I, Wih2, tid, NT2);
    load_wmat_h(smem_h + HW2H, Whh2, tid, NT2);
    load_wmat_h(smem_h + HW3I, Wih3, tid, NT2);
    load_wmat_h(smem_h + HW3H, Whh3, tid, NT2);
    {   // FC (fp32): o = g*32+jj (pad o=95), k = c*4+q; src Wfc[o*32+k]
        float* dst = smem + OWFC;
        for (int idx = tid; idx < 3 * 8 * 128; idx += NT2) {
            int q = idx & 3, jj = (idx >> 2) & 31;
            int c = (idx >> 7) % 8, g = idx / (8 * 128);
            int o = g * 32 + jj, k = c * 4 + q;
            dst[idx] = (o < VOC) ? Wfc[o * 32 + k] : 0.f;
        }
    }
    // zero h-state (h0 = 0)
    for (int idx = tid; idx < K2_SMEM_FLOATS - OFF_HS; idx += NT2)
        smem[OFF_HS + idx] = 0.f;
    __syncthreads();

    const int w = tid >> 5, j = tid & 31;
    const int gw = blockIdx.x * NW + w;
    const int rb = gw * 4;             // 4 batch rows per warp

    float2* hsw = (float2*)(smem + OFF_HS) + (size_t)w * (3 * 2 * 32);

    // per-lane bias packs (biases stay fp32 exact)
    ull bh1R = pk2(bhh1[j]), bh1Z = pk2(bhh1[32 + j]), bh1N = pk2(bhh1[64 + j]);
    ull bi2R = pk2(bih2[j]), bi2Z = pk2(bih2[32 + j]), bi2N = pk2(bih2[64 + j]);
    ull bh2R = pk2(bhh2[j]), bh2Z = pk2(bhh2[32 + j]), bh2N = pk2(bhh2[64 + j]);
    ull bi3R = pk2(bih3[j]), bi3Z = pk2(bih3[32 + j]), bi3N = pk2(bih3[64 + j]);
    ull bh3R = pk2(bhh3[j]), bh3Z = pk2(bhh3[32 + j]), bh3N = pk2(bhh3[64 + j]);
    float bf0 = (j      < VOC) ? bfc[j]      : 0.f;
    float bf1 = (32 + j < VOC) ? bfc[32 + j] : 0.f;
    float bf2 = (64 + j < VOC) ? bfc[64 + j] : 0.f;
    ull bfc0 = pk2(bf0), bfc1 = pk2(bf1), bfc2 = pk2(bf2);

    // row bases into xp [row][t][96]
    const size_t xb0 = (size_t)(rb + 0) * TT * 96;
    const size_t xb1 = (size_t)(rb + 1) * TT * 96;
    const size_t xb2 = (size_t)(rb + 2) * TT * 96;
    const size_t xb3 = (size_t)(rb + 3) * TT * 96;

    ull cur[2][3];
#pragma unroll
    for (int g = 0; g < 3; g++) {
        int o = g * 32 + j;
        cur[0][g] = pkf(__ldcs(g_xp + xb0 + o), __ldcs(g_xp + xb1 + o));
        cur[1][g] = pkf(__ldcs(g_xp + xb2 + o), __ldcs(g_xp + xb3 + o));
    }

#pragma unroll 1
    for (int t = 0; t < TT; t++) {
        // prefetch xp[t+1]
        float nf[2][3][2];
        const int tn = t + 1;
        if (tn < TT) {
            const size_t toff = (size_t)tn * 96;
#pragma unroll
            for (int g = 0; g < 3; g++) {
                int o = g * 32 + j;
                nf[0][g][0] = __ldcs(g_xp + xb0 + toff + o);
                nf[0][g][1] = __ldcs(g_xp + xb1 + toff + o);
                nf[1][g][0] = __ldcs(g_xp + xb2 + toff + o);
                nf[1][g][1] = __ldcs(g_xp + xb3 + toff + o);
            }
        }

        // ---- Layer 1: hidden proj only (fp16); input proj from xp ----
        {
            ull hR0 = bh1R, hZ0 = bh1Z, hN0 = bh1N;
            ull hR1 = bh1R, hZ1 = bh1Z, hN1 = bh1N;
            proj3h(smem_h + HW1H, j, hsw + 0, hsw + 32,
                   hR0, hZ0, hN0, hR1, hZ1, hN1);
            ull h0 = *(const ull*)(hsw + j);
            ull h1 = *(const ull*)(hsw + 32 + j);
            __syncwarp();
            ull n0 = gru_pair(add2(cur[0][0], hR0), add2(cur[0][1], hZ0),
                              cur[0][2], hN0, h0);
            ull n1 = gru_pair(add2(cur[1][0], hR1), add2(cur[1][1], hZ1),
                              cur[1][2], hN1, h1);
            *(ull*)(hsw + j) = n0;
            *(ull*)(hsw + 32 + j) = n1;
            __syncwarp();
        }

        layer_step_h(smem_h + HW2I, smem_h + HW2H, hsw + 0, hsw + 32,
                     hsw + 64,  j, bi2R, bi2Z, bi2N, bh2R, bh2Z, bh2N);
        layer_step_h(smem_h + HW3I, smem_h + HW3H, hsw + 64, hsw + 96,
                     hsw + 128, j, bi3R, bi3Z, bi3N, bh3R, bh3Z, bh3N);

        // FC head (fp32 weights)
        {
            ull a00 = bfc0, a10 = bfc1, a20 = bfc2;
            ull a01 = bfc0, a11 = bfc1, a21 = bfc2;
            proj3f(smem + OWFC, j, hsw + 128, hsw + 160,
                   a00, a10, a20, a01, a11, a21);
            float2 v;
            size_t base0 = ((size_t)(rb + 0) * TT + t) * VOC;
            size_t base1 = ((size_t)(rb + 1) * TT + t) * VOC;
            size_t base2 = ((size_t)(rb + 2) * TT + t) * VOC;
            size_t base3 = ((size_t)(rb + 3) * TT + t) * VOC;
            int o0 = j, o1 = 32 + j, o2 = 64 + j;
            v = up2(a00); __stcs(out + base0 + o0, v.x); __stcs(out + base1 + o0, v.y);
            v = up2(a01); __stcs(out + base2 + o0, v.x); __stcs(out + base3 + o0, v.y);
            v = up2(a10); __stcs(out + base0 + o1, v.x); __stcs(out + base1 + o1, v.y);
            v = up2(a11); __stcs(out + base2 + o1, v.x); __stcs(out + base3 + o1, v.y);
            if (o2 < VOC) {
                v = up2(a20); __stcs(out + base0 + o2, v.x); __stcs(out + base1 + o2, v.y);
                v = up2(a21); __stcs(out + base2 + o2, v.x); __stcs(out + base3 + o2, v.y);
            }
        }

        if (tn < TT) {
#pragma unroll
            for (int g = 0; g < 3; g++) {
                cur[0][g] = pkf(nf[0][g][0], nf[0][g][1]);
                cur[1][g] = pkf(nf[1][g][0], nf[1][g][1]);
            }
        }
    }
}

extern "C" void kernel_launch(void* const* d_in, const int* in_sizes, int n_in,
                              void* d_out, int out_size)
{
    const float* x    = (const float*)d_in[0];
    const float* Wih1 = (const float*)d_in[1];
    const float* Whh1 = (const float*)d_in[2];
    const float* bih1 = (const float*)d_in[3];
    const float* bhh1 = (const float*)d_in[4];
    const float* Wih2 = (const float*)d_in[5];
    const float* Whh2 = (const float*)d_in[6];
    const float* bih2 = (const float*)d_in[7];
    const float* bhh2 = (const float*)d_in[8];
    const float* Wih3 = (const float*)d_in[9];
    const float* Whh3 = (const float*)d_in[10];
    const float* bih3 = (const float*)d_in[11];
    const float* bhh3 = (const float*)d_in[12];
    const float* Wfc  = (const float*)d_in[13];
    const float* bfc  = (const float*)d_in[14];
    float* out = (float*)d_out;

    cudaFuncSetAttribute(gru_xproj, cudaFuncAttributeMaxDynamicSharedMemorySize,
                         K1_SMEM_BYTES);
    cudaFuncSetAttribute(gru_scan, cudaFuncAttributeMaxDynamicSharedMemorySize,
                         K2_SMEM_BYTES);

    gru_xproj<<<K1_NB, K1_NT, K1_SMEM_BYTES>>>(x, Wih1, bih1);
    gru_scan<<<NB, NT2, K2_SMEM_BYTES>>>(Whh1, bhh1,
                                         Wih2, Whh2, bih2, bhh2,
                                         Wih3, Whh3, bih3, bhh3,
                                         Wfc, bfc, out);
}

// round 10
// speedup vs baseline: 2.1999x; 1.1645x over previous
#include <cuda_runtime.h>
#include <cuda_fp16.h>
#include <cstdint>

using ull = unsigned long long;

#define VOC 95
#define TT  256
#define BB  2048

// ---------------- scratch: xp = x @ Wih1^T + bih1  [B*T, 96] ----------------
__device__ float g_xp[(size_t)BB * TT * 96];

// ---------- packed fp32x2 helpers ----------
__device__ __forceinline__ ull pk2(float w) {
    ull d; unsigned r = __float_as_uint(w);
    asm("mov.b64 %0, {%1,%1};" : "=l"(d) : "r"(r));
    return d;
}
__device__ __forceinline__ ull pkf(float a, float b) {
    ull d;
    asm("mov.b64 %0, {%1,%2};" : "=l"(d)
        : "r"(__float_as_uint(a)), "r"(__float_as_uint(b)));
    return d;
}
__device__ __forceinline__ float2 up2(ull v) {
    unsigned lo, hi;
    asm("mov.b64 {%0,%1}, %2;" : "=r"(lo), "=r"(hi) : "l"(v));
    return make_float2(__uint_as_float(lo), __uint_as_float(hi));
}
__device__ __forceinline__ void fma2(ull& d, ull a, ull b) {
    asm("fma.rn.f32x2 %0, %1, %2, %0;" : "+l"(d) : "l"(a), "l"(b));
}
__device__ __forceinline__ ull add2(ull a, ull b) {
    ull d; asm("add.rn.f32x2 %0, %1, %2;" : "=l"(d) : "l"(a), "l"(b));
    return d;
}

// ---------- activations ----------
__device__ __forceinline__ float tanhap(float v) {
    float r; asm("tanh.approx.f32 %0, %1;" : "=f"(r) : "f"(v)); return r;
}
__device__ __forceinline__ float fsig(float v) {
    return fmaf(tanhap(0.5f * v), 0.5f, 0.5f);
}

extern __shared__ float smem[];

// GMEM weight [3*32, isz] -> SMEM fp32 [g][c][lane][4]
__device__ __forceinline__ void load_wmat(float* dst, const float* __restrict__ src,
                                          int C, int isz, int tid, int nthr)
{
    int n = 3 * C * 128;
    for (int idx = tid; idx < n; idx += nthr) {
        int q = idx & 3, jj = (idx >> 2) & 31;
        int c = (idx >> 7) % C, g = idx / (C * 128);
        int i = c * 4 + q;
        dst[idx] = (i < isz) ? src[(g * 32 + jj) * isz + i] : 0.f;
    }
}

// GMEM weight [3*32, 32] -> SMEM fp16 [g][c][lane][4]
__device__ __forceinline__ void load_wmat_h(__half* dst, const float* __restrict__ src,
                                            int tid, int nthr)
{
    const int n = 3 * 8 * 128;
    for (int idx = tid; idx < n; idx += nthr) {
        int q = idx & 3, jj = (idx >> 2) & 31;
        int c = (idx >> 7) % 8, g = idx / (8 * 128);
        int i = c * 4 + q;
        dst[idx] = __float2half_rn(src[(g * 32 + jj) * 32 + i]);
    }
}

// ============================================================================
// Kernel 1: xp = x @ Wih1^T + bih1  (unchanged, proven 213 us)
// ============================================================================
#define K1_NB   256
#define K1_NT   256
#define K1_XS   9216
#define K1_SMEM_FLOATS (9216 + 8 * 8 * 96 * 2)
#define K1_SMEM_BYTES  (K1_SMEM_FLOATS * 4)

__global__ void __launch_bounds__(K1_NT, 2)
gru_xproj(const float* __restrict__ x,
          const float* __restrict__ Wih1,
          const float* __restrict__ bih1)
{
    const int tid = threadIdx.x;
    load_wmat(smem, Wih1, 24, VOC, tid, K1_NT);
    __syncthreads();

    const int w = tid >> 5, j = tid & 31;
    float2* xsw = (float2*)(smem + K1_XS) + (size_t)w * (8 * 96);

    const ull bR = pk2(bih1[j]), bZ = pk2(bih1[32 + j]), bN = pk2(bih1[64 + j]);
    const size_t pairBase = ((size_t)blockIdx.x * 8 + w) * 128;

#pragma unroll 1
    for (int it = 0; it < 16; it++) {
        const size_t p0 = pairBase + (size_t)it * 8;
#pragma unroll
        for (int p = 0; p < 8; p++) {
            size_t r0 = (p0 + p) * 2, r1 = r0 + 1;
#pragma unroll
            for (int k = 0; k < 3; k++) {
                int i = j + 32 * k;
                float a = 0.f, b = 0.f;
                if (i < VOC) {
                    a = __ldcs(x + r0 * VOC + i);
                    b = __ldcs(x + r1 * VOC + i);
                }
                xsw[p * 96 + i] = make_float2(a, b);
            }
        }
        __syncwarp();

        ull acc[8][3];
#pragma unroll
        for (int p = 0; p < 8; p++) { acc[p][0] = bR; acc[p][1] = bZ; acc[p][2] = bN; }

#pragma unroll 2
        for (int c = 0; c < 24; c++) {
            float4 wA = *(const float4*)(smem + ((0 * 24 + c) * 32 + j) * 4);
            float4 wB = *(const float4*)(smem + ((1 * 24 + c) * 32 + j) * 4);
            float4 wC = *(const float4*)(smem + ((2 * 24 + c) * 32 + j) * 4);
            ull a0 = pk2(wA.x), a1 = pk2(wA.y), a2 = pk2(wA.z), a3 = pk2(wA.w);
            ull b0 = pk2(wB.x), b1 = pk2(wB.y), b2 = pk2(wB.z), b3 = pk2(wB.w);
            ull c0 = pk2(wC.x), c1 = pk2(wC.y), c2 = pk2(wC.z), c3 = pk2(wC.w);
#pragma unroll
            for (int p = 0; p < 8; p++) {
                ulonglong2 x01 = *(const ulonglong2*)(xsw + p * 96 + 4 * c);
                ulonglong2 x23 = *(const ulonglong2*)(xsw + p * 96 + 4 * c + 2);
                fma2(acc[p][0], x01.x, a0); fma2(acc[p][0], x01.y, a1);
                fma2(acc[p][0], x23.x, a2); fma2(acc[p][0], x23.y, a3);
                fma2(acc[p][1], x01.x, b0); fma2(acc[p][1], x01.y, b1);
                fma2(acc[p][1], x23.x, b2); fma2(acc[p][1], x23.y, b3);
                fma2(acc[p][2], x01.x, c0); fma2(acc[p][2], x01.y, c1);
                fma2(acc[p][2], x23.x, c2); fma2(acc[p][2], x23.y, c3);
            }
        }

#pragma unroll
        for (int p = 0; p < 8; p++) {
            size_t r0 = (p0 + p) * 2, r1 = r0 + 1;
#pragma unroll
            for (int g = 0; g < 3; g++) {
                float2 v = up2(acc[p][g]);
                g_xp[r0 * 96 + g * 32 + j] = v.x;
                g_xp[r1 * 96 + g * 32 + j] = v.y;
            }
        }
        __syncwarp();
    }
}

// ============================================================================
// Kernel 2: scan with producer/consumer warp pairs.
// A-warp (wid 0-3): L1h + L2 for 4 rows.  B-warp (wid 4-7): L3 + FC, 1 step behind.
// A-warp g and B-warp g land on SMSP g (wid % 4) -> 2 warps/SMSP, disjoint weights.
// ============================================================================
#define NT2 256
#define NB  128

// half offsets
#define HW1H 0
#define HW2I 3072
#define HW2H 6144
#define HW3I 9216
#define HW3H 12288
// float offsets
#define OWFC 7680      // fp32 FC [3][8][32][4] = 3072 floats
#define OH1  10752     // float2 h1[4 grp][2 pair][32]   = 512 floats
#define OH2  11264     // float2 h2[4 grp][2 slot][2 pair][32] = 1024 floats
#define OH3  12288     // float2 h3[4 grp][2 pair][32]   = 512 floats
#define OFLG 12800     // int flags[4 grp][8]  (0 = ca, 4 = cb)
#define K2_SMEM_FLOATS 12832
#define K2_SMEM_BYTES  (K2_SMEM_FLOATS * 4)

__device__ __forceinline__ void h4tof(uint2 w, float2& lo, float2& hi) {
    lo = __half22float2(*reinterpret_cast<__half2*>(&w.x));
    hi = __half22float2(*reinterpret_cast<__half2*>(&w.y));
}

// fp16 weights, 8 chunks, 2 packed pairs
__device__ __forceinline__ void proj3h(const __half* __restrict__ W, int j,
                                       const float2* __restrict__ in0,
                                       const float2* __restrict__ in1,
                                       ull& aA0, ull& aB0, ull& aC0,
                                       ull& aA1, ull& aB1, ull& aC1)
{
#pragma unroll
    for (int c = 0; c < 8; c++) {
        uint2 hA = *(const uint2*)(W + ((0 * 8 + c) * 32 + j) * 4);
        uint2 hB = *(const uint2*)(W + ((1 * 8 + c) * 32 + j) * 4);
        uint2 hC = *(const uint2*)(W + ((2 * 8 + c) * 32 + j) * 4);
        ulonglong2 x01 = *(const ulonglong2*)(in0 + 4 * c);
        ulonglong2 x23 = *(const ulonglong2*)(in0 + 4 * c + 2);
        ulonglong2 y01 = *(const ulonglong2*)(in1 + 4 * c);
        ulonglong2 y23 = *(const ulonglong2*)(in1 + 4 * c + 2);
        float2 A01, A23, B01, B23, C01, C23;
        h4tof(hA, A01, A23); h4tof(hB, B01, B23); h4tof(hC, C01, C23);
        ull w;
        w = pk2(A01.x); fma2(aA0, x01.x, w); fma2(aA1, y01.x, w);
        w = pk2(A01.y); fma2(aA0, x01.y, w); fma2(aA1, y01.y, w);
        w = pk2(A23.x); fma2(aA0, x23.x, w); fma2(aA1, y23.x, w);
        w = pk2(A23.y); fma2(aA0, x23.y, w); fma2(aA1, y23.y, w);
        w = pk2(B01.x); fma2(aB0, x01.x, w); fma2(aB1, y01.x, w);
        w = pk2(B01.y); fma2(aB0, x01.y, w); fma2(aB1, y01.y, w);
        w = pk2(B23.x); fma2(aB0, x23.x, w); fma2(aB1, y23.x, w);
        w = pk2(B23.y); fma2(aB0, x23.y, w); fma2(aB1, y23.y, w);
        w = pk2(C01.x); fma2(aC0, x01.x, w); fma2(aC1, y01.x, w);
        w = pk2(C01.y); fma2(aC0, x01.y, w); fma2(aC1, y01.y, w);
        w = pk2(C23.x); fma2(aC0, x23.x, w); fma2(aC1, y23.x, w);
        w = pk2(C23.y); fma2(aC0, x23.y, w); fma2(aC1, y23.y, w);
    }
}

// fp32 weights, 8 chunks, 2 packed pairs (FC)
__device__ __forceinline__ void proj3f(const float* __restrict__ W, int j,
                                       const float2* __restrict__ in0,
                                       const float2* __restrict__ in1,
                                       ull& aA0, ull& aB0, ull& aC0,
                                       ull& aA1, ull& aB1, ull& aC1)
{
#pragma unroll
    for (int c = 0; c < 8; c++) {
        float4 wA = *(const float4*)(W + ((0 * 8 + c) * 32 + j) * 4);
        float4 wB = *(const float4*)(W + ((1 * 8 + c) * 32 + j) * 4);
        float4 wC = *(const float4*)(W + ((2 * 8 + c) * 32 + j) * 4);
        ulonglong2 x01 = *(const ulonglong2*)(in0 + 4 * c);
        ulonglong2 x23 = *(const ulonglong2*)(in0 + 4 * c + 2);
        ulonglong2 y01 = *(const ulonglong2*)(in1 + 4 * c);
        ulonglong2 y23 = *(const ulonglong2*)(in1 + 4 * c + 2);
        ull w;
        w = pk2(wA.x); fma2(aA0, x01.x, w); fma2(aA1, y01.x, w);
        w = pk2(wA.y); fma2(aA0, x01.y, w); fma2(aA1, y01.y, w);
        w = pk2(wA.z); fma2(aA0, x23.x, w); fma2(aA1, y23.x, w);
        w = pk2(wA.w); fma2(aA0, x23.y, w); fma2(aA1, y23.y, w);
        w = pk2(wB.x); fma2(aB0, x01.x, w); fma2(aB1, y01.x, w);
        w = pk2(wB.y); fma2(aB0, x01.y, w); fma2(aB1, y01.y, w);
        w = pk2(wB.z); fma2(aB0, x23.x, w); fma2(aB1, y23.x, w);
        w = pk2(wB.w); fma2(aB0, x23.y, w); fma2(aB1, y23.y, w);
        w = pk2(wC.x); fma2(aC0, x01.x, w); fma2(aC1, y01.x, w);
        w = pk2(wC.y); fma2(aC0, x01.y, w); fma2(aC1, y01.y, w);
        w = pk2(wC.z); fma2(aC0, x23.x, w); fma2(aC1, y23.x, w);
        w = pk2(wC.w); fma2(aC0, x23.y, w); fma2(aC1, y23.y, w);
    }
}

__device__ __forceinline__ ull gru_pair(ull aR, ull aZ, ull aNx, ull aNh, ull h)
{
    float2 r2 = up2(aR), z2 = up2(aZ), nx = up2(aNx), nh = up2(aNh), hh = up2(h);
    float r0 = fsig(r2.x), r1 = fsig(r2.y);
    float z0 = fsig(z2.x), z1 = fsig(z2.y);
    float n0 = tanhap(nx.x + r0 * nh.x);
    float n1 = tanhap(nx.y + r1 * nh.y);
    float h0 = n0 + z0 * (hh.x - n0);
    float h1 = n1 + z1 * (hh.y - n1);
    return pkf(h0, h1);
}

__device__ __forceinline__ void wait_ge(volatile int* f, int target) {
    if (*f >= target) return;
    while (*f < target) __nanosleep(40);
}

__global__ void __launch_bounds__(NT2, 1)
gru_scan(const float* __restrict__ Whh1, const float* __restrict__ bhh1,
         const float* __restrict__ Wih2, const float* __restrict__ Whh2,
         const float* __restrict__ bih2, const float* __restrict__ bhh2,
         const float* __restrict__ Wih3, const float* __restrict__ Whh3,
         const float* __restrict__ bih3, const float* __restrict__ bhh3,
         const float* __restrict__ Wfc,  const float* __restrict__ bfc,
         float* __restrict__ out)
{
    const int tid = threadIdx.x;
    __half* const smem_h = (__half*)smem;

    load_wmat_h(smem_h + HW1H, Whh1, tid, NT2);
    load_wmat_h(smem_h + HW2I, Wih2, tid, NT2);
    load_wmat_h(smem_h + HW2H, Whh2, tid, NT2);
    load_wmat_h(smem_h + HW3I, Wih3, tid, NT2);
    load_wmat_h(smem_h + HW3H, Whh3, tid, NT2);
    {
        float* dst = smem + OWFC;
        for (int idx = tid; idx < 3 * 8 * 128; idx += NT2) {
            int q = idx & 3, jj = (idx >> 2) & 31;
            int c = (idx >> 7) % 8, g = idx / (8 * 128);
            int o = g * 32 + jj, k = c * 4 + q;
            dst[idx] = (o < VOC) ? Wfc[o * 32 + k] : 0.f;
        }
    }
    // zero h states + rings + flags
    for (int idx = tid; idx < K2_SMEM_FLOATS - OH1; idx += NT2)
        smem[OH1 + idx] = 0.f;
    __syncthreads();

    const int w = tid >> 5, j = tid & 31;
    const int g = w & 3;
    const int rb = blockIdx.x * 16 + g * 4;   // this group's 4 rows
    float2* const h1b = (float2*)(smem + OH1) + g * 64;
    float2* const h2b = (float2*)(smem + OH2) + g * 128;
    float2* const h3b = (float2*)(smem + OH3) + g * 64;
    volatile int* const flg = (volatile int*)(smem + OFLG) + g * 8; // [0]=ca [4]=cb

    if (w < 4) {
        // ===================== A: L1h + L2 =====================
        ull bh1R = pk2(bhh1[j]), bh1Z = pk2(bhh1[32 + j]), bh1N = pk2(bhh1[64 + j]);
        ull bi2R = pk2(bih2[j]), bi2Z = pk2(bih2[32 + j]), bi2N = pk2(bih2[64 + j]);
        ull bh2R = pk2(bhh2[j]), bh2Z = pk2(bhh2[32 + j]), bh2N = pk2(bhh2[64 + j]);

        const size_t xb0 = (size_t)(rb + 0) * TT * 96;
        const size_t xb1 = (size_t)(rb + 1) * TT * 96;
        const size_t xb2 = (size_t)(rb + 2) * TT * 96;
        const size_t xb3 = (size_t)(rb + 3) * TT * 96;

        ull cur[2][3];
#pragma unroll
        for (int gg = 0; gg < 3; gg++) {
            int o = gg * 32 + j;
            cur[0][gg] = pkf(__ldcs(g_xp + xb0 + o), __ldcs(g_xp + xb1 + o));
            cur[1][gg] = pkf(__ldcs(g_xp + xb2 + o), __ldcs(g_xp + xb3 + o));
        }

#pragma unroll 1
        for (int t = 0; t < TT; t++) {
            float nf[2][3][2];
            const int tn = t + 1;
            if (tn < TT) {
                const size_t toff = (size_t)tn * 96;
#pragma unroll
                for (int gg = 0; gg < 3; gg++) {
                    int o = gg * 32 + j;
                    nf[0][gg][0] = __ldcs(g_xp + xb0 + toff + o);
                    nf[0][gg][1] = __ldcs(g_xp + xb1 + toff + o);
                    nf[1][gg][0] = __ldcs(g_xp + xb2 + toff + o);
                    nf[1][gg][1] = __ldcs(g_xp + xb3 + toff + o);
                }
            }

            // ---- L1: hidden proj + ew with xp ----
            {
                ull hR0 = bh1R, hZ0 = bh1Z, hN0 = bh1N;
                ull hR1 = bh1R, hZ1 = bh1Z, hN1 = bh1N;
                proj3h(smem_h + HW1H, j, h1b, h1b + 32,
                       hR0, hZ0, hN0, hR1, hZ1, hN1);
                ull h0 = *(const ull*)(h1b + j);
                ull h1p = *(const ull*)(h1b + 32 + j);
                __syncwarp();
                ull n0 = gru_pair(add2(cur[0][0], hR0), add2(cur[0][1], hZ0),
                                  cur[0][2], hN0, h0);
                ull n1 = gru_pair(add2(cur[1][0], hR1), add2(cur[1][1], hZ1),
                                  cur[1][2], hN1, h1p);
                *(ull*)(h1b + j) = n0;
                *(ull*)(h1b + 32 + j) = n1;
                __syncwarp();
            }

            // ---- L2: input proj over h1, hidden proj over h2[t-1] ring ----
            ull xR0 = bi2R, xZ0 = bi2Z, xN0 = bi2N;
            ull xR1 = bi2R, xZ1 = bi2Z, xN1 = bi2N;
            proj3h(smem_h + HW2I, j, h1b, h1b + 32, xR0, xZ0, xN0, xR1, xZ1, xN1);

            const float2* h2o = h2b + ((t - 1) & 1) * 64;
            ull gR0 = bh2R, gZ0 = bh2Z, gN0 = bh2N;
            ull gR1 = bh2R, gZ1 = bh2Z, gN1 = bh2N;
            proj3h(smem_h + HW2H, j, h2o, h2o + 32, gR0, gZ0, gN0, gR1, gZ1, gN1);
            ull ho0 = *(const ull*)(h2o + j);
            ull ho1 = *(const ull*)(h2o + 32 + j);
            ull m0 = gru_pair(add2(xR0, gR0), add2(xZ0, gZ0), xN0, gN0, ho0);
            ull m1 = gru_pair(add2(xR1, gR1), add2(xZ1, gZ1), xN1, gN1, ho1);

            // B must be done reading slot t&1 (its step t-2)
            if (t >= 2) wait_ge(flg + 4, t - 1);
            float2* h2n = h2b + (t & 1) * 64;
            *(ull*)(h2n + j) = m0;
            *(ull*)(h2n + 32 + j) = m1;
            __threadfence_block();
            __syncwarp();
            if (j == 0) flg[0] = t + 1;

            if (tn < TT) {
#pragma unroll
                for (int gg = 0; gg < 3; gg++) {
                    cur[0][gg] = pkf(nf[0][gg][0], nf[0][gg][1]);
                    cur[1][gg] = pkf(nf[1][gg][0], nf[1][gg][1]);
                }
            }
        }
    } else {
        // ===================== B: L3 + FC (1 step behind) =====================
        ull bi3R = pk2(bih3[j]), bi3Z = pk2(bih3[32 + j]), bi3N = pk2(bih3[64 + j]);
        ull bh3R = pk2(bhh3[j]), bh3Z = pk2(bhh3[32 + j]), bh3N = pk2(bhh3[64 + j]);
        float bf0f = (j      < VOC) ? bfc[j]      : 0.f;
        float bf1f = (32 + j < VOC) ? bfc[32 + j] : 0.f;
        float bf2f = (64 + j < VOC) ? bfc[64 + j] : 0.f;
        ull bfc0 = pk2(bf0f), bfc1 = pk2(bf1f), bfc2 = pk2(bf2f);

#pragma unroll 1
        for (int s = 0; s < TT; s++) {
            wait_ge(flg, s + 1);
            __threadfence_block();

            // ---- L3 input proj over h2[s] ----
            const float2* h2s = h2b + (s & 1) * 64;
            ull xR0 = bi3R, xZ0 = bi3Z, xN0 = bi3N;
            ull xR1 = bi3R, xZ1 = bi3Z, xN1 = bi3N;
            proj3h(smem_h + HW3I, j, h2s, h2s + 32, xR0, xZ0, xN0, xR1, xZ1, xN1);
            __threadfence_block();
            __syncwarp();
            if (j == 0) flg[4] = s + 1;    // release h2 slot back to A

            // ---- L3 hidden proj + ew ----
            ull gR0 = bh3R, gZ0 = bh3Z, gN0 = bh3N;
            ull gR1 = bh3R, gZ1 = bh3Z, gN1 = bh3N;
            proj3h(smem_h + HW3H, j, h3b, h3b + 32, gR0, gZ0, gN0, gR1, gZ1, gN1);
            ull ho0 = *(const ull*)(h3b + j);
            ull ho1 = *(const ull*)(h3b + 32 + j);
            __syncwarp();
            ull n0 = gru_pair(add2(xR0, gR0), add2(xZ0, gZ0), xN0, gN0, ho0);
            ull n1 = gru_pair(add2(xR1, gR1), add2(xZ1, gZ1), xN1, gN1, ho1);
            *(ull*)(h3b + j) = n0;
            *(ull*)(h3b + 32 + j) = n1;
            __syncwarp();

            // ---- FC head (fp32) ----
            ull a00 = bfc0, a10 = bfc1, a20 = bfc2;
            ull a01 = bfc0, a11 = bfc1, a21 = bfc2;
            proj3f(smem + OWFC, j, h3b, h3b + 32, a00, a10, a20, a01, a11, a21);
            float2 v;
            size_t base0 = ((size_t)(rb + 0) * TT + s) * VOC;
            size_t base1 = ((size_t)(rb + 1) * TT + s) * VOC;
            size_t base2 = ((size_t)(rb + 2) * TT + s) * VOC;
            size_t base3 = ((size_t)(rb + 3) * TT + s) * VOC;
            int o0 = j, o1 = 32 + j, o2 = 64 + j;
            v = up2(a00); __stcs(out + base0 + o0, v.x); __stcs(out + base1 + o0, v.y);
            v = up2(a01); __stcs(out + base2 + o0, v.x); __stcs(out + base3 + o0, v.y);
            v = up2(a10); __stcs(out + base0 + o1, v.x); __stcs(out + base1 + o1, v.y);
            v = up2(a11); __stcs(out + base2 + o1, v.x); __stcs(out + base3 + o1, v.y);
            if (o2 < VOC) {
                v = up2(a20); __stcs(out + base0 + o2, v.x); __stcs(out + base1 + o2, v.y);
                v = up2(a21); __stcs(out + base2 + o2, v.x); __stcs(out + base3 + o2, v.y);
            }
        }
    }
}

extern "C" void kernel_launch(void* const* d_in, const int* in_sizes, int n_in,
                              void* d_out, int out_size)
{
    const float* x    = (const float*)d_in[0];
    const float* Wih1 = (const float*)d_in[1];
    const float* Whh1 = (const float*)d_in[2];
    const float* bih1 = (const float*)d_in[3];
    const float* bhh1 = (const float*)d_in[4];
    const float* Wih2 = (const float*)d_in[5];
    const float* Whh2 = (const float*)d_in[6];
    const float* bih2 = (const float*)d_in[7];
    const float* bhh2 = (const float*)d_in[8];
    const float* Wih3 = (const float*)d_in[9];
    const float* Whh3 = (const float*)d_in[10];
    const float* bih3 = (const float*)d_in[11];
    const float* bhh3 = (const float*)d_in[12];
    const float* Wfc  = (const float*)d_in[13];
    const float* bfc  = (const float*)d_in[14];
    float* out = (float*)d_out;

    cudaFuncSetAttribute(gru_xproj, cudaFuncAttributeMaxDynamicSharedMemorySize,
                         K1_SMEM_BYTES);
    cudaFuncSetAttribute(gru_scan, cudaFuncAttributeMaxDynamicSharedMemorySize,
                         K2_SMEM_BYTES);

    gru_xproj<<<K1_NB, K1_NT, K1_SMEM_BYTES>>>(x, Wih1, bih1);
    gru_scan<<<NB, NT2, K2_SMEM_BYTES>>>(Whh1, bhh1,
                                         Wih2, Whh2, bih2, bhh2,
                                         Wih3, Whh3, bih3, bhh3,
                                         Wfc, bfc, out);
}